// round 1
// baseline (speedup 1.0000x reference)
#include <cuda_runtime.h>
#include <cuda_bf16.h>

#define N_NODES 50000
#define N_EDGES 600000
#define IN_FEATS 16
#define H 128
#define N_CLASSES 4
#define N_HIDDEN 19

// ---------------- scratch (device globals; no allocation allowed) ----------------
__device__ float g_bufA[N_NODES * H];
__device__ float g_bufZ[N_NODES * H];
__device__ int   g_deg[N_NODES];
__device__ int   g_cnt[N_NODES];
__device__ int   g_row_ptr[N_NODES + 1];
__device__ float g_deg_inv[N_NODES];
__device__ int   g_csr_src[N_EDGES];
__device__ float g_csr_w[N_EDGES];

// ---------------- preprocessing ----------------
__global__ void zero_counts_kernel() {
    int i = blockIdx.x * blockDim.x + threadIdx.x;
    if (i < N_NODES) { g_deg[i] = 0; g_cnt[i] = 0; }
}

__global__ void hist_kernel(const int* __restrict__ dst) {
    int i = blockIdx.x * blockDim.x + threadIdx.x;
    if (i < N_EDGES) atomicAdd(&g_deg[dst[i]], 1);
}

// single-block exclusive scan over 50000 degrees; also writes deg_inv
__global__ void scan_kernel() {
    __shared__ int sums[1024];
    const int n = N_NODES;
    int tid = threadIdx.x;
    const int chunk = (n + 1023) / 1024;
    int beg = tid * chunk;
    int end = beg + chunk; if (end > n) end = n;
    int s = 0;
    for (int i = beg; i < end; i++) s += g_deg[i];
    sums[tid] = s;
    __syncthreads();
    // inclusive Hillis-Steele
    for (int off = 1; off < 1024; off <<= 1) {
        int v = 0;
        if (tid >= off) v = sums[tid - off];
        __syncthreads();
        sums[tid] += v;
        __syncthreads();
    }
    int prefix = (tid == 0) ? 0 : sums[tid - 1];
    for (int i = beg; i < end; i++) {
        g_row_ptr[i] = prefix;
        int d = g_deg[i];
        prefix += d;
        g_deg_inv[i] = 1.0f / fmaxf((float)d, 1.0f);
    }
    if (tid == 0) g_row_ptr[n] = sums[1023];
}

__global__ void fill_kernel(const int* __restrict__ src, const int* __restrict__ dst,
                            const float* __restrict__ ew) {
    int i = blockIdx.x * blockDim.x + threadIdx.x;
    if (i < N_EDGES) {
        int d = dst[i];
        int pos = g_row_ptr[d] + atomicAdd(&g_cnt[d], 1);
        g_csr_src[pos] = src[i];
        g_csr_w[pos]   = ew[i];
    }
}

// ---------------- GEMM: C[M,128] = A[M,K] @ W[K,128] + bias ----------------
template<int K>
__global__ void gemm_bias_kernel(const float* __restrict__ A, const float* __restrict__ W,
                                 const float* __restrict__ bias, float* __restrict__ C, int M)
{
    const int BK = 16;
    __shared__ float As[BK][H + 1];  // +1 pad: 2-way max conflict on transposed store
    __shared__ float Ws[BK][H];
    int tid = threadIdx.x;
    int tx = tid & 15;
    int ty = tid >> 4;
    int m0 = blockIdx.x * H;

    float acc[8][8];
#pragma unroll
    for (int r = 0; r < 8; r++)
#pragma unroll
        for (int c = 0; c < 8; c++) acc[r][c] = 0.f;

    for (int k0 = 0; k0 < K; k0 += BK) {
#pragma unroll
        for (int i = tid; i < H * BK; i += 256) {
            int m = i >> 4, k = i & 15;
            int gm = m0 + m;
            As[k][m] = (gm < M) ? A[gm * K + k0 + k] : 0.f;
        }
#pragma unroll
        for (int i = tid; i < BK * H; i += 256) {
            int k = i >> 7, n = i & (H - 1);
            Ws[k][n] = W[(k0 + k) * H + n];
        }
        __syncthreads();
#pragma unroll
        for (int k = 0; k < BK; k++) {
            float a[8], w[8];
#pragma unroll
            for (int r = 0; r < 8; r++) a[r] = As[k][ty + r * 16];
#pragma unroll
            for (int c = 0; c < 8; c++) w[c] = Ws[k][tx + c * 16];
#pragma unroll
            for (int r = 0; r < 8; r++)
#pragma unroll
                for (int c = 0; c < 8; c++)
                    acc[r][c] += a[r] * w[c];
        }
        __syncthreads();
    }
#pragma unroll
    for (int r = 0; r < 8; r++) {
        int gm = m0 + ty + r * 16;
        if (gm < M) {
#pragma unroll
            for (int c = 0; c < 8; c++) {
                int n = tx + c * 16;
                C[gm * H + n] = acc[r][c] + bias[n];
            }
        }
    }
}

// ---------------- aggregation: out[v] = leaky( deg_inv[v] * sum_e w_e * z[src_e] ) ----------------
__global__ void agg_leaky_kernel(const float* __restrict__ z, float* __restrict__ out)
{
    int node = blockIdx.x;
    int f = threadIdx.x;
    int beg = g_row_ptr[node];
    int end = g_row_ptr[node + 1];
    float acc = 0.f;
    int e = beg;
    // unroll-by-4 for MLP over L2 latency
    for (; e + 4 <= end; e += 4) {
        int s0 = g_csr_src[e + 0];
        int s1 = g_csr_src[e + 1];
        int s2 = g_csr_src[e + 2];
        int s3 = g_csr_src[e + 3];
        float w0 = g_csr_w[e + 0];
        float w1 = g_csr_w[e + 1];
        float w2 = g_csr_w[e + 2];
        float w3 = g_csr_w[e + 3];
        float z0 = z[s0 * H + f];
        float z1 = z[s1 * H + f];
        float z2 = z[s2 * H + f];
        float z3 = z[s3 * H + f];
        acc += z0 * w0 + z1 * w1 + z2 * w2 + z3 * w3;
    }
    for (; e < end; e++) {
        int s = g_csr_src[e];
        acc += z[s * H + f] * g_csr_w[e];
    }
    acc *= g_deg_inv[node];
    out[node * H + f] = (acc > 0.f) ? acc : 0.01f * acc;
}

// ---------------- final FC: out[M,4] = h[M,128] @ Wfc[128,4] + bfc ----------------
__global__ void fc_kernel(const float* __restrict__ h, const float* __restrict__ Wfc,
                          const float* __restrict__ bfc, float* __restrict__ out, int M)
{
    int warp = (blockIdx.x * blockDim.x + threadIdx.x) >> 5;
    int lane = threadIdx.x & 31;
    if (warp >= M) return;
    const float* hr = h + (size_t)warp * H;
    float acc0 = 0.f, acc1 = 0.f, acc2 = 0.f, acc3 = 0.f;
#pragma unroll
    for (int k = lane; k < H; k += 32) {
        float hv = hr[k];
        acc0 += hv * Wfc[k * 4 + 0];
        acc1 += hv * Wfc[k * 4 + 1];
        acc2 += hv * Wfc[k * 4 + 2];
        acc3 += hv * Wfc[k * 4 + 3];
    }
#pragma unroll
    for (int off = 16; off; off >>= 1) {
        acc0 += __shfl_down_sync(0xffffffffu, acc0, off);
        acc1 += __shfl_down_sync(0xffffffffu, acc1, off);
        acc2 += __shfl_down_sync(0xffffffffu, acc2, off);
        acc3 += __shfl_down_sync(0xffffffffu, acc3, off);
    }
    if (lane == 0) {
        out[warp * 4 + 0] = acc0 + bfc[0];
        out[warp * 4 + 1] = acc1 + bfc[1];
        out[warp * 4 + 2] = acc2 + bfc[2];
        out[warp * 4 + 3] = acc3 + bfc[3];
    }
}

// ---------------- launch ----------------
extern "C" void kernel_launch(void* const* d_in, const int* in_sizes, int n_in,
                              void* d_out, int out_size)
{
    const float* x          = (const float*)d_in[0];
    const int*   edge_index = (const int*)d_in[1];
    const float* edge_attr  = (const float*)d_in[2];
    const float* W_in       = (const float*)d_in[3];
    const float* b_in       = (const float*)d_in[4];
    const float* W_h        = (const float*)d_in[5];
    const float* b_h        = (const float*)d_in[6];
    const float* W_fc       = (const float*)d_in[7];
    const float* b_fc       = (const float*)d_in[8];
    float* out = (float*)d_out;

    const int* src = edge_index;            // row 0
    const int* dst = edge_index + N_EDGES;  // row 1

    float *bufA, *bufZ;
    cudaGetSymbolAddress((void**)&bufA, g_bufA);
    cudaGetSymbolAddress((void**)&bufZ, g_bufZ);

    // preprocessing: degree, CSR
    zero_counts_kernel<<<(N_NODES + 255) / 256, 256>>>();
    hist_kernel<<<(N_EDGES + 255) / 256, 256>>>(dst);
    scan_kernel<<<1, 1024>>>();
    fill_kernel<<<(N_EDGES + 255) / 256, 256>>>(src, dst, edge_attr);

    const int GEMM_GRID = (N_NODES + H - 1) / H;

    // layer 0: x [N,16] -> bufZ -> agg -> bufA
    gemm_bias_kernel<IN_FEATS><<<GEMM_GRID, 256>>>(x, W_in, b_in, bufZ, N_NODES);
    agg_leaky_kernel<<<N_NODES, H>>>(bufZ, bufA);

    // 19 hidden layers
    for (int l = 0; l < N_HIDDEN; l++) {
        gemm_bias_kernel<H><<<GEMM_GRID, 256>>>(bufA, W_h + (size_t)l * H * H,
                                                b_h + (size_t)l * H, bufZ, N_NODES);
        agg_leaky_kernel<<<N_NODES, H>>>(bufZ, bufA);
    }

    // final FC: [N,128] @ [128,4] + b
    const int FC_THREADS = 256;
    const int warps_per_block = FC_THREADS / 32;
    fc_kernel<<<(N_NODES + warps_per_block - 1) / warps_per_block, FC_THREADS>>>(
        bufA, W_fc, b_fc, out, N_NODES);
}

// round 2
// speedup vs baseline: 1.2586x; 1.2586x over previous
#include <cuda_runtime.h>
#include <cuda_bf16.h>

#define N_NODES 50000
#define N_EDGES 600000
#define IN_FEATS 16
#define H 128
#define N_CLASSES 4
#define N_HIDDEN 19

// ---------------- scratch (device globals; no allocation allowed) ----------------
__device__ float g_bufA[N_NODES * H];
__device__ float g_bufZ[N_NODES * H];
__device__ int   g_deg[N_NODES];
__device__ int   g_cnt[N_NODES];
__device__ int   g_row_ptr[N_NODES + 1];
__device__ float g_deg_inv[N_NODES];
__device__ int   g_csr_src[N_EDGES];
__device__ float g_csr_w[N_EDGES];

// ---------------- preprocessing ----------------
__global__ void zero_counts_kernel() {
    int i = blockIdx.x * blockDim.x + threadIdx.x;
    if (i < N_NODES) { g_deg[i] = 0; g_cnt[i] = 0; }
}

__global__ void hist_kernel(const int* __restrict__ dst) {
    int i = blockIdx.x * blockDim.x + threadIdx.x;
    if (i < N_EDGES) atomicAdd(&g_deg[dst[i]], 1);
}

// single-block exclusive scan over 50000 degrees; also writes deg_inv
__global__ void scan_kernel() {
    __shared__ int sums[1024];
    const int n = N_NODES;
    int tid = threadIdx.x;
    const int chunk = (n + 1023) / 1024;
    int beg = tid * chunk;
    int end = beg + chunk; if (end > n) end = n;
    int s = 0;
    for (int i = beg; i < end; i++) s += g_deg[i];
    sums[tid] = s;
    __syncthreads();
    for (int off = 1; off < 1024; off <<= 1) {
        int v = 0;
        if (tid >= off) v = sums[tid - off];
        __syncthreads();
        sums[tid] += v;
        __syncthreads();
    }
    int prefix = (tid == 0) ? 0 : sums[tid - 1];
    for (int i = beg; i < end; i++) {
        g_row_ptr[i] = prefix;
        int d = g_deg[i];
        prefix += d;
        g_deg_inv[i] = 1.0f / fmaxf((float)d, 1.0f);
    }
    if (tid == 0) g_row_ptr[n] = sums[1023];
}

__global__ void fill_kernel(const int* __restrict__ src, const int* __restrict__ dst,
                            const float* __restrict__ ew) {
    int i = blockIdx.x * blockDim.x + threadIdx.x;
    if (i < N_EDGES) {
        int d = dst[i];
        int pos = g_row_ptr[d] + atomicAdd(&g_cnt[d], 1);
        g_csr_src[pos] = src[i];
        g_csr_w[pos]   = ew[i];
    }
}

// ---------------- GEMM: C[M,128] = A[M,K] @ W[K,128] + bias -------------------
// Packed f32x2 FMA version: each thread owns an 8-row x 4-colpair register tile.
// fma.rn.f32x2 = 2 exact fp32 FMAs per lane per instruction (sm_100+ only via PTX).
template<int K>
__global__ void __launch_bounds__(256)
gemm_bias_kernel(const float* __restrict__ A, const float* __restrict__ W,
                 const float* __restrict__ bias, float* __restrict__ C, int M)
{
    const int BK = 16;
    __shared__ float As[BK][H + 1];   // transposed A tile (k-major), pad vs conflicts
    __shared__ float Ws[BK][H];       // W tile, row = k, 8B-aligned rows (H even)
    int tid = threadIdx.x;
    int tx = tid & 15;                // column-pair group: pairs at n = 2*tx + 32*c
    int ty = tid >> 4;                // row group:          rows  m = ty + 16*r
    int m0 = blockIdx.x * H;

    unsigned long long acc[8][4];
#pragma unroll
    for (int r = 0; r < 8; r++)
#pragma unroll
        for (int c = 0; c < 4; c++) acc[r][c] = 0ull;

    for (int k0 = 0; k0 < K; k0 += BK) {
#pragma unroll
        for (int i = tid; i < H * BK; i += 256) {
            int m = i >> 4, k = i & 15;
            int gm = m0 + m;
            As[k][m] = (gm < M) ? A[gm * K + k0 + k] : 0.f;
        }
#pragma unroll
        for (int i = tid; i < BK * H; i += 256) {
            int k = i >> 7, n = i & (H - 1);
            Ws[k][n] = W[(k0 + k) * H + n];
        }
        __syncthreads();
#pragma unroll
        for (int k = 0; k < BK; k++) {
            unsigned long long ad[8];
#pragma unroll
            for (int r = 0; r < 8; r++) {
                float av = As[k][ty + r * 16];           // broadcast within warp
                asm("mov.b64 %0, {%1, %1};" : "=l"(ad[r]) : "f"(av));
            }
            unsigned long long wd[4];
#pragma unroll
            for (int c = 0; c < 4; c++) {
                // 64-bit LDS of an adjacent column pair; conflict-free across lanes
                wd[c] = *reinterpret_cast<const unsigned long long*>(&Ws[k][2 * tx + 32 * c]);
            }
#pragma unroll
            for (int r = 0; r < 8; r++)
#pragma unroll
                for (int c = 0; c < 4; c++)
                    asm("fma.rn.f32x2 %0, %1, %2, %0;"
                        : "+l"(acc[r][c]) : "l"(ad[r]), "l"(wd[c]));
        }
        __syncthreads();
    }

#pragma unroll
    for (int r = 0; r < 8; r++) {
        int gm = m0 + ty + r * 16;
        if (gm < M) {
#pragma unroll
            for (int c = 0; c < 4; c++) {
                int n = 2 * tx + 32 * c;
                float lo, hi;
                asm("mov.b64 {%0, %1}, %2;" : "=f"(lo), "=f"(hi) : "l"(acc[r][c]));
                float2 bv = *reinterpret_cast<const float2*>(&bias[n]);
                float2 o; o.x = lo + bv.x; o.y = hi + bv.y;
                *reinterpret_cast<float2*>(&C[gm * H + n]) = o;
            }
        }
    }
}

// ---------------- aggregation: out[v] = leaky( deg_inv[v] * sum_e w_e * z[src_e] ) --
__global__ void agg_leaky_kernel(const float* __restrict__ z, float* __restrict__ out)
{
    int node = blockIdx.x;
    int f = threadIdx.x;
    int beg = g_row_ptr[node];
    int end = g_row_ptr[node + 1];
    float acc = 0.f;
    int e = beg;
    for (; e + 4 <= end; e += 4) {
        int s0 = g_csr_src[e + 0];
        int s1 = g_csr_src[e + 1];
        int s2 = g_csr_src[e + 2];
        int s3 = g_csr_src[e + 3];
        float w0 = g_csr_w[e + 0];
        float w1 = g_csr_w[e + 1];
        float w2 = g_csr_w[e + 2];
        float w3 = g_csr_w[e + 3];
        float z0 = z[s0 * H + f];
        float z1 = z[s1 * H + f];
        float z2 = z[s2 * H + f];
        float z3 = z[s3 * H + f];
        acc += z0 * w0 + z1 * w1 + z2 * w2 + z3 * w3;
    }
    for (; e < end; e++) {
        int s = g_csr_src[e];
        acc += z[s * H + f] * g_csr_w[e];
    }
    acc *= g_deg_inv[node];
    out[node * H + f] = (acc > 0.f) ? acc : 0.01f * acc;
}

// ---------------- final FC: out[M,4] = h[M,128] @ Wfc[128,4] + bfc ----------------
__global__ void fc_kernel(const float* __restrict__ h, const float* __restrict__ Wfc,
                          const float* __restrict__ bfc, float* __restrict__ out, int M)
{
    int warp = (blockIdx.x * blockDim.x + threadIdx.x) >> 5;
    int lane = threadIdx.x & 31;
    if (warp >= M) return;
    const float* hr = h + (size_t)warp * H;
    float acc0 = 0.f, acc1 = 0.f, acc2 = 0.f, acc3 = 0.f;
#pragma unroll
    for (int k = lane; k < H; k += 32) {
        float hv = hr[k];
        acc0 += hv * Wfc[k * 4 + 0];
        acc1 += hv * Wfc[k * 4 + 1];
        acc2 += hv * Wfc[k * 4 + 2];
        acc3 += hv * Wfc[k * 4 + 3];
    }
#pragma unroll
    for (int off = 16; off; off >>= 1) {
        acc0 += __shfl_down_sync(0xffffffffu, acc0, off);
        acc1 += __shfl_down_sync(0xffffffffu, acc1, off);
        acc2 += __shfl_down_sync(0xffffffffu, acc2, off);
        acc3 += __shfl_down_sync(0xffffffffu, acc3, off);
    }
    if (lane == 0) {
        out[warp * 4 + 0] = acc0 + bfc[0];
        out[warp * 4 + 1] = acc1 + bfc[1];
        out[warp * 4 + 2] = acc2 + bfc[2];
        out[warp * 4 + 3] = acc3 + bfc[3];
    }
}

// ---------------- launch ----------------
extern "C" void kernel_launch(void* const* d_in, const int* in_sizes, int n_in,
                              void* d_out, int out_size)
{
    const float* x          = (const float*)d_in[0];
    const int*   edge_index = (const int*)d_in[1];
    const float* edge_attr  = (const float*)d_in[2];
    const float* W_in       = (const float*)d_in[3];
    const float* b_in       = (const float*)d_in[4];
    const float* W_h        = (const float*)d_in[5];
    const float* b_h        = (const float*)d_in[6];
    const float* W_fc       = (const float*)d_in[7];
    const float* b_fc       = (const float*)d_in[8];
    float* out = (float*)d_out;

    const int* src = edge_index;            // row 0
    const int* dst = edge_index + N_EDGES;  // row 1

    float *bufA, *bufZ;
    cudaGetSymbolAddress((void**)&bufA, g_bufA);
    cudaGetSymbolAddress((void**)&bufZ, g_bufZ);

    // preprocessing: degree, CSR
    zero_counts_kernel<<<(N_NODES + 255) / 256, 256>>>();
    hist_kernel<<<(N_EDGES + 255) / 256, 256>>>(dst);
    scan_kernel<<<1, 1024>>>();
    fill_kernel<<<(N_EDGES + 255) / 256, 256>>>(src, dst, edge_attr);

    const int GEMM_GRID = (N_NODES + H - 1) / H;

    // layer 0: x [N,16] -> bufZ -> agg -> bufA
    gemm_bias_kernel<IN_FEATS><<<GEMM_GRID, 256>>>(x, W_in, b_in, bufZ, N_NODES);
    agg_leaky_kernel<<<N_NODES, H>>>(bufZ, bufA);

    // 19 hidden layers
    for (int l = 0; l < N_HIDDEN; l++) {
        gemm_bias_kernel<H><<<GEMM_GRID, 256>>>(bufA, W_h + (size_t)l * H * H,
                                                b_h + (size_t)l * H, bufZ, N_NODES);
        agg_leaky_kernel<<<N_NODES, H>>>(bufZ, bufA);
    }

    // final FC: [N,128] @ [128,4] + b
    const int FC_THREADS = 256;
    const int warps_per_block = FC_THREADS / 32;
    fc_kernel<<<(N_NODES + warps_per_block - 1) / warps_per_block, FC_THREADS>>>(
        bufA, W_fc, b_fc, out, N_NODES);
}

// round 3
// speedup vs baseline: 1.5889x; 1.2624x over previous
#include <cuda_runtime.h>
#include <cuda_bf16.h>

#define N_NODES 50000
#define N_EDGES 600000
#define IN_FEATS 16
#define H 128
#define N_CLASSES 4
#define N_HIDDEN 19

// ---------------- scratch (device globals; no allocation allowed) ----------------
__device__ float g_bufA[N_NODES * H];
__device__ float g_bufZ[N_NODES * H];
__device__ int   g_deg[N_NODES];
__device__ int   g_cnt[N_NODES];
__device__ int   g_row_ptr[N_NODES + 1];
__device__ float g_deg_inv[N_NODES];
__device__ int2  g_csr[N_EDGES];      // {src, float_as_int(w)} packed per edge

// ---------------- preprocessing ----------------
__global__ void zero_counts_kernel() {
    int i = blockIdx.x * blockDim.x + threadIdx.x;
    if (i < N_NODES) { g_deg[i] = 0; g_cnt[i] = 0; }
}

__global__ void hist_kernel(const int* __restrict__ dst) {
    int i = blockIdx.x * blockDim.x + threadIdx.x;
    if (i < N_EDGES) atomicAdd(&g_deg[dst[i]], 1);
}

// single-block exclusive scan over 50000 degrees; also writes deg_inv
__global__ void scan_kernel() {
    __shared__ int sums[1024];
    const int n = N_NODES;
    int tid = threadIdx.x;
    const int chunk = (n + 1023) / 1024;
    int beg = tid * chunk;
    int end = beg + chunk; if (end > n) end = n;
    int s = 0;
    for (int i = beg; i < end; i++) s += g_deg[i];
    sums[tid] = s;
    __syncthreads();
    for (int off = 1; off < 1024; off <<= 1) {
        int v = 0;
        if (tid >= off) v = sums[tid - off];
        __syncthreads();
        sums[tid] += v;
        __syncthreads();
    }
    int prefix = (tid == 0) ? 0 : sums[tid - 1];
    for (int i = beg; i < end; i++) {
        g_row_ptr[i] = prefix;
        int d = g_deg[i];
        prefix += d;
        g_deg_inv[i] = 1.0f / fmaxf((float)d, 1.0f);
    }
    if (tid == 0) g_row_ptr[n] = sums[1023];
}

__global__ void fill_kernel(const int* __restrict__ src, const int* __restrict__ dst,
                            const float* __restrict__ ew) {
    int i = blockIdx.x * blockDim.x + threadIdx.x;
    if (i < N_EDGES) {
        int d = dst[i];
        int pos = g_row_ptr[d] + atomicAdd(&g_cnt[d], 1);
        g_csr[pos] = make_int2(src[i], __float_as_int(ew[i]));
    }
}

// ---------------- GEMM: C[M,128] = A[M,K] @ W[K,128] + bias -------------------
// Packed f32x2 FMA version: each thread owns an 8-row x 4-colpair register tile.
template<int K>
__global__ void __launch_bounds__(256)
gemm_bias_kernel(const float* __restrict__ A, const float* __restrict__ W,
                 const float* __restrict__ bias, float* __restrict__ C, int M)
{
    const int BK = 16;
    __shared__ float As[BK][H + 1];
    __shared__ float Ws[BK][H];
    int tid = threadIdx.x;
    int tx = tid & 15;                // column-pair group: pairs at n = 2*tx + 32*c
    int ty = tid >> 4;                // row group:          rows  m = ty + 16*r
    int m0 = blockIdx.x * H;

    unsigned long long acc[8][4];
#pragma unroll
    for (int r = 0; r < 8; r++)
#pragma unroll
        for (int c = 0; c < 4; c++) acc[r][c] = 0ull;

    for (int k0 = 0; k0 < K; k0 += BK) {
#pragma unroll
        for (int i = tid; i < H * BK; i += 256) {
            int m = i >> 4, k = i & 15;
            int gm = m0 + m;
            As[k][m] = (gm < M) ? A[gm * K + k0 + k] : 0.f;
        }
#pragma unroll
        for (int i = tid; i < BK * H; i += 256) {
            int k = i >> 7, n = i & (H - 1);
            Ws[k][n] = W[(k0 + k) * H + n];
        }
        __syncthreads();
#pragma unroll
        for (int k = 0; k < BK; k++) {
            unsigned long long ad[8];
#pragma unroll
            for (int r = 0; r < 8; r++) {
                float av = As[k][ty + r * 16];
                asm("mov.b64 %0, {%1, %1};" : "=l"(ad[r]) : "f"(av));
            }
            unsigned long long wd[4];
#pragma unroll
            for (int c = 0; c < 4; c++) {
                wd[c] = *reinterpret_cast<const unsigned long long*>(&Ws[k][2 * tx + 32 * c]);
            }
#pragma unroll
            for (int r = 0; r < 8; r++)
#pragma unroll
                for (int c = 0; c < 4; c++)
                    asm("fma.rn.f32x2 %0, %1, %2, %0;"
                        : "+l"(acc[r][c]) : "l"(ad[r]), "l"(wd[c]));
        }
        __syncthreads();
    }

#pragma unroll
    for (int r = 0; r < 8; r++) {
        int gm = m0 + ty + r * 16;
        if (gm < M) {
#pragma unroll
            for (int c = 0; c < 4; c++) {
                int n = 2 * tx + 32 * c;
                float lo, hi;
                asm("mov.b64 {%0, %1}, %2;" : "=f"(lo), "=f"(hi) : "l"(acc[r][c]));
                float2 bv = *reinterpret_cast<const float2*>(&bias[n]);
                float2 o; o.x = lo + bv.x; o.y = hi + bv.y;
                *reinterpret_cast<float2*>(&C[gm * H + n]) = o;
            }
        }
    }
}

// ---------------- aggregation: warp per node, float4 per lane -----------------
// out[v] = leaky( deg_inv[v] * sum_e w_e * z[src_e] )
__global__ void __launch_bounds__(256)
agg_leaky_kernel(const float4* __restrict__ z4, float4* __restrict__ out4)
{
    int node = blockIdx.x * 8 + (threadIdx.x >> 5);
    if (node >= N_NODES) return;
    int lane = threadIdx.x & 31;
    int beg = g_row_ptr[node];
    int end = g_row_ptr[node + 1];

    float4 acc = make_float4(0.f, 0.f, 0.f, 0.f);
    int e = beg;
    for (; e + 4 <= end; e += 4) {
        // warp-uniform broadcast loads of packed edge records (L1 broadcast)
        int2 p0 = __ldg(&g_csr[e + 0]);
        int2 p1 = __ldg(&g_csr[e + 1]);
        int2 p2 = __ldg(&g_csr[e + 2]);
        int2 p3 = __ldg(&g_csr[e + 3]);
        // 4 independent row gathers -> MLP=4 over L2 latency
        float4 z0 = z4[p0.x * 32 + lane];
        float4 z1 = z4[p1.x * 32 + lane];
        float4 z2 = z4[p2.x * 32 + lane];
        float4 z3 = z4[p3.x * 32 + lane];
        float w0 = __int_as_float(p0.y);
        float w1 = __int_as_float(p1.y);
        float w2 = __int_as_float(p2.y);
        float w3 = __int_as_float(p3.y);
        acc.x += z0.x * w0 + z1.x * w1 + z2.x * w2 + z3.x * w3;
        acc.y += z0.y * w0 + z1.y * w1 + z2.y * w2 + z3.y * w3;
        acc.z += z0.z * w0 + z1.z * w1 + z2.z * w2 + z3.z * w3;
        acc.w += z0.w * w0 + z1.w * w1 + z2.w * w2 + z3.w * w3;
    }
    for (; e < end; e++) {
        int2 p = __ldg(&g_csr[e]);
        float4 zv = z4[p.x * 32 + lane];
        float w = __int_as_float(p.y);
        acc.x += zv.x * w; acc.y += zv.y * w;
        acc.z += zv.z * w; acc.w += zv.w * w;
    }
    float di = g_deg_inv[node];
    acc.x *= di; acc.y *= di; acc.z *= di; acc.w *= di;
    acc.x = (acc.x > 0.f) ? acc.x : 0.01f * acc.x;
    acc.y = (acc.y > 0.f) ? acc.y : 0.01f * acc.y;
    acc.z = (acc.z > 0.f) ? acc.z : 0.01f * acc.z;
    acc.w = (acc.w > 0.f) ? acc.w : 0.01f * acc.w;
    out4[node * 32 + lane] = acc;
}

// ---------------- final FC: out[M,4] = h[M,128] @ Wfc[128,4] + bfc ----------------
__global__ void fc_kernel(const float* __restrict__ h, const float* __restrict__ Wfc,
                          const float* __restrict__ bfc, float* __restrict__ out, int M)
{
    int warp = (blockIdx.x * blockDim.x + threadIdx.x) >> 5;
    int lane = threadIdx.x & 31;
    if (warp >= M) return;
    const float* hr = h + (size_t)warp * H;
    float acc0 = 0.f, acc1 = 0.f, acc2 = 0.f, acc3 = 0.f;
#pragma unroll
    for (int k = lane; k < H; k += 32) {
        float hv = hr[k];
        acc0 += hv * Wfc[k * 4 + 0];
        acc1 += hv * Wfc[k * 4 + 1];
        acc2 += hv * Wfc[k * 4 + 2];
        acc3 += hv * Wfc[k * 4 + 3];
    }
#pragma unroll
    for (int off = 16; off; off >>= 1) {
        acc0 += __shfl_down_sync(0xffffffffu, acc0, off);
        acc1 += __shfl_down_sync(0xffffffffu, acc1, off);
        acc2 += __shfl_down_sync(0xffffffffu, acc2, off);
        acc3 += __shfl_down_sync(0xffffffffu, acc3, off);
    }
    if (lane == 0) {
        out[warp * 4 + 0] = acc0 + bfc[0];
        out[warp * 4 + 1] = acc1 + bfc[1];
        out[warp * 4 + 2] = acc2 + bfc[2];
        out[warp * 4 + 3] = acc3 + bfc[3];
    }
}

// ---------------- launch ----------------
extern "C" void kernel_launch(void* const* d_in, const int* in_sizes, int n_in,
                              void* d_out, int out_size)
{
    const float* x          = (const float*)d_in[0];
    const int*   edge_index = (const int*)d_in[1];
    const float* edge_attr  = (const float*)d_in[2];
    const float* W_in       = (const float*)d_in[3];
    const float* b_in       = (const float*)d_in[4];
    const float* W_h        = (const float*)d_in[5];
    const float* b_h        = (const float*)d_in[6];
    const float* W_fc       = (const float*)d_in[7];
    const float* b_fc       = (const float*)d_in[8];
    float* out = (float*)d_out;

    const int* src = edge_index;            // row 0
    const int* dst = edge_index + N_EDGES;  // row 1

    float *bufA, *bufZ;
    cudaGetSymbolAddress((void**)&bufA, g_bufA);
    cudaGetSymbolAddress((void**)&bufZ, g_bufZ);

    // preprocessing: degree, CSR
    zero_counts_kernel<<<(N_NODES + 255) / 256, 256>>>();
    hist_kernel<<<(N_EDGES + 255) / 256, 256>>>(dst);
    scan_kernel<<<1, 1024>>>();
    fill_kernel<<<(N_EDGES + 255) / 256, 256>>>(src, dst, edge_attr);

    const int GEMM_GRID = (N_NODES + H - 1) / H;
    const int AGG_GRID  = (N_NODES + 7) / 8;

    // layer 0: x [N,16] -> bufZ -> agg -> bufA
    gemm_bias_kernel<IN_FEATS><<<GEMM_GRID, 256>>>(x, W_in, b_in, bufZ, N_NODES);
    agg_leaky_kernel<<<AGG_GRID, 256>>>((const float4*)bufZ, (float4*)bufA);

    // 19 hidden layers
    for (int l = 0; l < N_HIDDEN; l++) {
        gemm_bias_kernel<H><<<GEMM_GRID, 256>>>(bufA, W_h + (size_t)l * H * H,
                                                b_h + (size_t)l * H, bufZ, N_NODES);
        agg_leaky_kernel<<<AGG_GRID, 256>>>((const float4*)bufZ, (float4*)bufA);
    }

    // final FC: [N,128] @ [128,4] + b
    const int FC_THREADS = 256;
    const int warps_per_block = FC_THREADS / 32;
    fc_kernel<<<(N_NODES + warps_per_block - 1) / warps_per_block, FC_THREADS>>>(
        bufA, W_fc, b_fc, out, N_NODES);
}

// round 4
// speedup vs baseline: 1.7861x; 1.1241x over previous
#include <cuda_runtime.h>
#include <cuda_fp16.h>

#define N_NODES 50000
#define N_EDGES 600000
#define IN_FEATS 16
#define H 128
#define N_CLASSES 4
#define N_HIDDEN 19

// ---------------- scratch (device globals; no allocation allowed) ----------------
__device__ float  g_bufA[N_NODES * H];          // fp32 h (agg output / GEMM input)
__device__ __half g_bufZ[N_NODES * H];          // fp16 z (GEMM output / agg gather src)
__device__ int    g_deg[N_NODES];
__device__ int    g_cnt[N_NODES];
__device__ int    g_row_ptr[N_NODES + 1];
__device__ float  g_deg_inv[N_NODES];
__device__ int2   g_csr[N_EDGES];               // {src, float_as_int(w)} packed per edge

// ---------------- preprocessing ----------------
__global__ void zero_counts_kernel() {
    int i = blockIdx.x * blockDim.x + threadIdx.x;
    if (i < N_NODES) { g_deg[i] = 0; g_cnt[i] = 0; }
}

__global__ void hist_kernel(const int* __restrict__ dst) {
    int i = blockIdx.x * blockDim.x + threadIdx.x;
    if (i < N_EDGES) atomicAdd(&g_deg[dst[i]], 1);
}

// single-block exclusive scan over 50000 degrees; also writes deg_inv
__global__ void scan_kernel() {
    __shared__ int sums[1024];
    const int n = N_NODES;
    int tid = threadIdx.x;
    const int chunk = (n + 1023) / 1024;
    int beg = tid * chunk;
    int end = beg + chunk; if (end > n) end = n;
    int s = 0;
    for (int i = beg; i < end; i++) s += g_deg[i];
    sums[tid] = s;
    __syncthreads();
    for (int off = 1; off < 1024; off <<= 1) {
        int v = 0;
        if (tid >= off) v = sums[tid - off];
        __syncthreads();
        sums[tid] += v;
        __syncthreads();
    }
    int prefix = (tid == 0) ? 0 : sums[tid - 1];
    for (int i = beg; i < end; i++) {
        g_row_ptr[i] = prefix;
        int d = g_deg[i];
        prefix += d;
        g_deg_inv[i] = 1.0f / fmaxf((float)d, 1.0f);
    }
    if (tid == 0) g_row_ptr[n] = sums[1023];
}

__global__ void fill_kernel(const int* __restrict__ src, const int* __restrict__ dst,
                            const float* __restrict__ ew) {
    int i = blockIdx.x * blockDim.x + threadIdx.x;
    if (i < N_EDGES) {
        int d = dst[i];
        int pos = g_row_ptr[d] + atomicAdd(&g_cnt[d], 1);
        g_csr[pos] = make_int2(src[i], __float_as_int(ew[i]));
    }
}

// ---------------- GEMM: Z[M,128] = A[M,K] @ W[K,128] + bias (fp32 acc, fp16 out) --
// Packed f32x2 FMA: each thread owns an 8-row x 4-colpair register tile.
template<int K>
__global__ void __launch_bounds__(256)
gemm_bias_kernel(const float* __restrict__ A, const float* __restrict__ W,
                 const float* __restrict__ bias, __half2* __restrict__ Z, int M)
{
    const int BK = 16;
    __shared__ float As[BK][H + 1];
    __shared__ float Ws[BK][H];
    int tid = threadIdx.x;
    int tx = tid & 15;                // column-pair group: pairs at n = 2*tx + 32*c
    int ty = tid >> 4;                // row group:          rows  m = ty + 16*r
    int m0 = blockIdx.x * H;

    unsigned long long acc[8][4];
#pragma unroll
    for (int r = 0; r < 8; r++)
#pragma unroll
        for (int c = 0; c < 4; c++) acc[r][c] = 0ull;

    for (int k0 = 0; k0 < K; k0 += BK) {
#pragma unroll
        for (int i = tid; i < H * BK; i += 256) {
            int m = i >> 4, k = i & 15;
            int gm = m0 + m;
            As[k][m] = (gm < M) ? A[gm * K + k0 + k] : 0.f;
        }
#pragma unroll
        for (int i = tid; i < BK * H; i += 256) {
            int k = i >> 7, n = i & (H - 1);
            Ws[k][n] = W[(k0 + k) * H + n];
        }
        __syncthreads();
#pragma unroll
        for (int k = 0; k < BK; k++) {
            unsigned long long ad[8];
#pragma unroll
            for (int r = 0; r < 8; r++) {
                float av = As[k][ty + r * 16];
                asm("mov.b64 %0, {%1, %1};" : "=l"(ad[r]) : "f"(av));
            }
            unsigned long long wd[4];
#pragma unroll
            for (int c = 0; c < 4; c++) {
                wd[c] = *reinterpret_cast<const unsigned long long*>(&Ws[k][2 * tx + 32 * c]);
            }
#pragma unroll
            for (int r = 0; r < 8; r++)
#pragma unroll
                for (int c = 0; c < 4; c++)
                    asm("fma.rn.f32x2 %0, %1, %2, %0;"
                        : "+l"(acc[r][c]) : "l"(ad[r]), "l"(wd[c]));
        }
        __syncthreads();
    }

#pragma unroll
    for (int r = 0; r < 8; r++) {
        int gm = m0 + ty + r * 16;
        if (gm < M) {
#pragma unroll
            for (int c = 0; c < 4; c++) {
                int n = 2 * tx + 32 * c;
                float lo, hi;
                asm("mov.b64 {%0, %1}, %2;" : "=f"(lo), "=f"(hi) : "l"(acc[r][c]));
                float2 bv = *reinterpret_cast<const float2*>(&bias[n]);
                Z[gm * (H / 2) + (n >> 1)] =
                    __float22half2_rn(make_float2(lo + bv.x, hi + bv.y));
            }
        }
    }
}

// ---------------- aggregation: warp per node, fp16 gathers --------------------
// out[v] = leaky( deg_inv[v] * sum_e w_e * z[src_e] );  z fp16, accum fp32
__global__ void __launch_bounds__(256)
agg_leaky_kernel(const uint2* __restrict__ z, float4* __restrict__ out4)
{
    int node = blockIdx.x * 8 + (threadIdx.x >> 5);
    if (node >= N_NODES) return;
    int lane = threadIdx.x & 31;   // lane owns features [4*lane, 4*lane+4)
    int beg = g_row_ptr[node];
    int end = g_row_ptr[node + 1];

    float4 acc = make_float4(0.f, 0.f, 0.f, 0.f);
    int e = beg;
    for (; e + 4 <= end; e += 4) {
        int2 p0 = __ldg(&g_csr[e + 0]);
        int2 p1 = __ldg(&g_csr[e + 1]);
        int2 p2 = __ldg(&g_csr[e + 2]);
        int2 p3 = __ldg(&g_csr[e + 3]);
        // 4 independent 8B gathers (half4 per lane) -> MLP=4 over L2 latency
        uint2 v0 = z[p0.x * 32 + lane];
        uint2 v1 = z[p1.x * 32 + lane];
        uint2 v2 = z[p2.x * 32 + lane];
        uint2 v3 = z[p3.x * 32 + lane];
        float w0 = __int_as_float(p0.y);
        float w1 = __int_as_float(p1.y);
        float w2 = __int_as_float(p2.y);
        float w3 = __int_as_float(p3.y);
        float2 a0 = __half22float2(*(const __half2*)&v0.x);
        float2 b0 = __half22float2(*(const __half2*)&v0.y);
        float2 a1 = __half22float2(*(const __half2*)&v1.x);
        float2 b1 = __half22float2(*(const __half2*)&v1.y);
        float2 a2 = __half22float2(*(const __half2*)&v2.x);
        float2 b2 = __half22float2(*(const __half2*)&v2.y);
        float2 a3 = __half22float2(*(const __half2*)&v3.x);
        float2 b3 = __half22float2(*(const __half2*)&v3.y);
        acc.x += a0.x * w0 + a1.x * w1 + a2.x * w2 + a3.x * w3;
        acc.y += a0.y * w0 + a1.y * w1 + a2.y * w2 + a3.y * w3;
        acc.z += b0.x * w0 + b1.x * w1 + b2.x * w2 + b3.x * w3;
        acc.w += b0.y * w0 + b1.y * w1 + b2.y * w2 + b3.y * w3;
    }
    for (; e < end; e++) {
        int2 p = __ldg(&g_csr[e]);
        uint2 v = z[p.x * 32 + lane];
        float w = __int_as_float(p.y);
        float2 a = __half22float2(*(const __half2*)&v.x);
        float2 b = __half22float2(*(const __half2*)&v.y);
        acc.x += a.x * w; acc.y += a.y * w;
        acc.z += b.x * w; acc.w += b.y * w;
    }
    float di = g_deg_inv[node];
    acc.x *= di; acc.y *= di; acc.z *= di; acc.w *= di;
    acc.x = (acc.x > 0.f) ? acc.x : 0.01f * acc.x;
    acc.y = (acc.y > 0.f) ? acc.y : 0.01f * acc.y;
    acc.z = (acc.z > 0.f) ? acc.z : 0.01f * acc.z;
    acc.w = (acc.w > 0.f) ? acc.w : 0.01f * acc.w;
    out4[node * 32 + lane] = acc;   // features [4*lane..4*lane+3] — row layout preserved
}

// ---------------- final FC: out[M,4] = h[M,128] @ Wfc[128,4] + bfc ----------------
__global__ void fc_kernel(const float* __restrict__ h, const float* __restrict__ Wfc,
                          const float* __restrict__ bfc, float* __restrict__ out, int M)
{
    int warp = (blockIdx.x * blockDim.x + threadIdx.x) >> 5;
    int lane = threadIdx.x & 31;
    if (warp >= M) return;
    const float* hr = h + (size_t)warp * H;
    float acc0 = 0.f, acc1 = 0.f, acc2 = 0.f, acc3 = 0.f;
#pragma unroll
    for (int k = lane; k < H; k += 32) {
        float hv = hr[k];
        acc0 += hv * Wfc[k * 4 + 0];
        acc1 += hv * Wfc[k * 4 + 1];
        acc2 += hv * Wfc[k * 4 + 2];
        acc3 += hv * Wfc[k * 4 + 3];
    }
#pragma unroll
    for (int off = 16; off; off >>= 1) {
        acc0 += __shfl_down_sync(0xffffffffu, acc0, off);
        acc1 += __shfl_down_sync(0xffffffffu, acc1, off);
        acc2 += __shfl_down_sync(0xffffffffu, acc2, off);
        acc3 += __shfl_down_sync(0xffffffffu, acc3, off);
    }
    if (lane == 0) {
        out[warp * 4 + 0] = acc0 + bfc[0];
        out[warp * 4 + 1] = acc1 + bfc[1];
        out[warp * 4 + 2] = acc2 + bfc[2];
        out[warp * 4 + 3] = acc3 + bfc[3];
    }
}

// ---------------- launch ----------------
extern "C" void kernel_launch(void* const* d_in, const int* in_sizes, int n_in,
                              void* d_out, int out_size)
{
    const float* x          = (const float*)d_in[0];
    const int*   edge_index = (const int*)d_in[1];
    const float* edge_attr  = (const float*)d_in[2];
    const float* W_in       = (const float*)d_in[3];
    const float* b_in       = (const float*)d_in[4];
    const float* W_h        = (const float*)d_in[5];
    const float* b_h        = (const float*)d_in[6];
    const float* W_fc       = (const float*)d_in[7];
    const float* b_fc       = (const float*)d_in[8];
    float* out = (float*)d_out;

    const int* src = edge_index;            // row 0
    const int* dst = edge_index + N_EDGES;  // row 1

    float *bufA; __half *bufZ;
    cudaGetSymbolAddress((void**)&bufA, g_bufA);
    cudaGetSymbolAddress((void**)&bufZ, g_bufZ);

    // preprocessing: degree, CSR
    zero_counts_kernel<<<(N_NODES + 255) / 256, 256>>>();
    hist_kernel<<<(N_EDGES + 255) / 256, 256>>>(dst);
    scan_kernel<<<1, 1024>>>();
    fill_kernel<<<(N_EDGES + 255) / 256, 256>>>(src, dst, edge_attr);

    const int GEMM_GRID = (N_NODES + H - 1) / H;
    const int AGG_GRID  = (N_NODES + 7) / 8;

    // layer 0: x [N,16] -> z (fp16) -> agg -> bufA (fp32)
    gemm_bias_kernel<IN_FEATS><<<GEMM_GRID, 256>>>(x, W_in, b_in, (__half2*)bufZ, N_NODES);
    agg_leaky_kernel<<<AGG_GRID, 256>>>((const uint2*)bufZ, (float4*)bufA);

    // 19 hidden layers
    for (int l = 0; l < N_HIDDEN; l++) {
        gemm_bias_kernel<H><<<GEMM_GRID, 256>>>(bufA, W_h + (size_t)l * H * H,
                                                b_h + (size_t)l * H, (__half2*)bufZ, N_NODES);
        agg_leaky_kernel<<<AGG_GRID, 256>>>((const uint2*)bufZ, (float4*)bufA);
    }

    // final FC: [N,128] @ [128,4] + b
    const int FC_THREADS = 256;
    const int warps_per_block = FC_THREADS / 32;
    fc_kernel<<<(N_NODES + warps_per_block - 1) / warps_per_block, FC_THREADS>>>(
        bufA, W_fc, b_fc, out, N_NODES);
}

// round 8
// speedup vs baseline: 3.0881x; 1.7290x over previous
#include <cuda_runtime.h>
#include <cuda_fp16.h>
#include <mma.h>

#define N_NODES 50000
#define N_EDGES 600000
#define IN_FEATS 16
#define H 128
#define N_CLASSES 4
#define N_HIDDEN 19

using namespace nvcuda;

// ---------------- scratch (device globals; no allocation allowed) ----------------
__device__ __half g_bufA[N_NODES * H];          // fp16 h (agg output / GEMM input)
__device__ __half g_bufZ[N_NODES * H];          // fp16 z (GEMM output / agg gather src)
__device__ __half g_Wh16[N_HIDDEN * H * H];     // fp16 hidden weights
__device__ int    g_deg[N_NODES];
__device__ int    g_cnt[N_NODES];
__device__ int    g_row_ptr[N_NODES + 1];
__device__ float  g_deg_inv[N_NODES];
__device__ int2   g_csr[N_EDGES];               // {src, float_as_int(w)} per edge

// ---------------- preprocessing ----------------
__global__ void zero_counts_kernel() {
    int i = blockIdx.x * blockDim.x + threadIdx.x;
    if (i < N_NODES) { g_deg[i] = 0; g_cnt[i] = 0; }
}

__global__ void hist_kernel(const int* __restrict__ dst) {
    int i = blockIdx.x * blockDim.x + threadIdx.x;
    if (i < N_EDGES) atomicAdd(&g_deg[dst[i]], 1);
}

__global__ void convert_w_kernel(const float* __restrict__ W) {
    int i = blockIdx.x * blockDim.x + threadIdx.x;
    if (i < N_HIDDEN * H * H) g_Wh16[i] = __float2half(W[i]);
}

// single-block exclusive scan over 50000 degrees; also writes deg_inv
__global__ void scan_kernel() {
    __shared__ int sums[1024];
    const int n = N_NODES;
    int tid = threadIdx.x;
    const int chunk = (n + 1023) / 1024;
    int beg = tid * chunk;
    int end = beg + chunk; if (end > n) end = n;
    int s = 0;
    for (int i = beg; i < end; i++) s += g_deg[i];
    sums[tid] = s;
    __syncthreads();
    for (int off = 1; off < 1024; off <<= 1) {
        int v = 0;
        if (tid >= off) v = sums[tid - off];
        __syncthreads();
        sums[tid] += v;
        __syncthreads();
    }
    int prefix = (tid == 0) ? 0 : sums[tid - 1];
    for (int i = beg; i < end; i++) {
        g_row_ptr[i] = prefix;
        int d = g_deg[i];
        prefix += d;
        g_deg_inv[i] = 1.0f / fmaxf((float)d, 1.0f);
    }
    if (tid == 0) g_row_ptr[n] = sums[1023];
}

__global__ void fill_kernel(const int* __restrict__ src, const int* __restrict__ dst,
                            const float* __restrict__ ew) {
    int i = blockIdx.x * blockDim.x + threadIdx.x;
    if (i < N_EDGES) {
        int d = dst[i];
        int pos = g_row_ptr[d] + atomicAdd(&g_cnt[d], 1);
        g_csr[pos] = make_int2(src[i], __float_as_int(ew[i]));
    }
}

// ---------------- layer-0 GEMM (fp32 in, FFMA2, fp16 out): K=16 ----------------
template<int K>
__global__ void __launch_bounds__(256)
gemm_bias_kernel(const float* __restrict__ A, const float* __restrict__ W,
                 const float* __restrict__ bias, __half2* __restrict__ Z, int M)
{
    const int BK = 16;
    __shared__ float As[BK][H + 1];
    __shared__ float Ws[BK][H];
    int tid = threadIdx.x;
    int tx = tid & 15;
    int ty = tid >> 4;
    int m0 = blockIdx.x * H;

    unsigned long long acc[8][4];
#pragma unroll
    for (int r = 0; r < 8; r++)
#pragma unroll
        for (int c = 0; c < 4; c++) acc[r][c] = 0ull;

    for (int k0 = 0; k0 < K; k0 += BK) {
#pragma unroll
        for (int i = tid; i < H * BK; i += 256) {
            int m = i >> 4, k = i & 15;
            int gm = m0 + m;
            As[k][m] = (gm < M) ? A[gm * K + k0 + k] : 0.f;
        }
#pragma unroll
        for (int i = tid; i < BK * H; i += 256) {
            int k = i >> 7, n = i & (H - 1);
            Ws[k][n] = W[(k0 + k) * H + n];
        }
        __syncthreads();
#pragma unroll
        for (int k = 0; k < BK; k++) {
            unsigned long long ad[8];
#pragma unroll
            for (int r = 0; r < 8; r++) {
                float av = As[k][ty + r * 16];
                asm("mov.b64 %0, {%1, %1};" : "=l"(ad[r]) : "f"(av));
            }
            unsigned long long wd[4];
#pragma unroll
            for (int c = 0; c < 4; c++) {
                wd[c] = *reinterpret_cast<const unsigned long long*>(&Ws[k][2 * tx + 32 * c]);
            }
#pragma unroll
            for (int r = 0; r < 8; r++)
#pragma unroll
                for (int c = 0; c < 4; c++)
                    asm("fma.rn.f32x2 %0, %1, %2, %0;"
                        : "+l"(acc[r][c]) : "l"(ad[r]), "l"(wd[c]));
        }
        __syncthreads();
    }

#pragma unroll
    for (int r = 0; r < 8; r++) {
        int gm = m0 + ty + r * 16;
        if (gm < M) {
#pragma unroll
            for (int c = 0; c < 4; c++) {
                int n = 2 * tx + 32 * c;
                float lo, hi;
                asm("mov.b64 {%0, %1}, %2;" : "=f"(lo), "=f"(hi) : "l"(acc[r][c]));
                float2 bv = *reinterpret_cast<const float2*>(&bias[n]);
                Z[gm * (H / 2) + (n >> 1)] =
                    __float22half2_rn(make_float2(lo + bv.x, hi + bv.y));
            }
        }
    }
}

// ---------------- hidden GEMM: Z[M,128] = h[M,128](fp16) @ Wh(fp16) + b, WMMA ----
// 128x128 tile per 256-thread block; warp w owns rows 16w..16w+15 x all 128 cols.
// K chunked by 32 through smem. wmma 16x16x16 fp16 -> fp32 accumulate.
#define AS_LD 40     // halfs per As row (32 + 8 pad), multiple of 8
#define WS_LD 136    // halfs per Ws row (128 + 8 pad), multiple of 8
#define CS_LD 20     // floats per staging row (16 + 4 pad), multiple of 4

__global__ void __launch_bounds__(256)
hgemm_kernel(const __half* __restrict__ A, const __half* __restrict__ Wh,
             const float* __restrict__ bias, __half2* __restrict__ Z, int M)
{
    __shared__ __align__(16) __half As[128 * AS_LD];
    __shared__ __align__(16) __half Ws[32 * WS_LD];
    __shared__ __align__(16) float  Cs[8][16 * CS_LD];
    int tid = threadIdx.x;
    int wid = tid >> 5;
    int lane = tid & 31;
    int m0 = blockIdx.x * 128;

    wmma::fragment<wmma::accumulator, 16, 16, 16, float> acc[8];
#pragma unroll
    for (int nb = 0; nb < 8; nb++) wmma::fill_fragment(acc[nb], 0.0f);

    for (int k0 = 0; k0 < H; k0 += 32) {
        // load A chunk: 128 rows x 32 halfs (512 uint4 of 8 halfs)
#pragma unroll
        for (int i = tid; i < 512; i += 256) {
            int ri = i >> 2, ci = i & 3;
            int gm = m0 + ri;
            uint4 v = make_uint4(0u, 0u, 0u, 0u);
            if (gm < M)
                v = *reinterpret_cast<const uint4*>(A + (size_t)gm * H + k0 + ci * 8);
            *reinterpret_cast<uint4*>(As + ri * AS_LD + ci * 8) = v;
        }
        // load W chunk: 32 rows x 128 halfs (512 uint4)
#pragma unroll
        for (int i = tid; i < 512; i += 256) {
            int ri = i >> 4, ci = i & 15;
            uint4 v = *reinterpret_cast<const uint4*>(Wh + (size_t)(k0 + ri) * H + ci * 8);
            *reinterpret_cast<uint4*>(Ws + ri * WS_LD + ci * 8) = v;
        }
        __syncthreads();

#pragma unroll
        for (int ks = 0; ks < 2; ks++) {
            wmma::fragment<wmma::matrix_a, 16, 16, 16, __half, wmma::row_major> af;
            wmma::load_matrix_sync(af, As + (wid * 16) * AS_LD + ks * 16, AS_LD);
#pragma unroll
            for (int nb = 0; nb < 8; nb++) {
                wmma::fragment<wmma::matrix_b, 16, 16, 16, __half, wmma::row_major> bf;
                wmma::load_matrix_sync(bf, Ws + (ks * 16) * WS_LD + nb * 16, WS_LD);
                wmma::mma_sync(acc[nb], af, bf, acc[nb]);
            }
        }
        __syncthreads();
    }

    // epilogue: stage each 16x16 accum tile through smem, add bias, fp16 out
#pragma unroll
    for (int nb = 0; nb < 8; nb++) {
        wmma::store_matrix_sync(&Cs[wid][0], acc[nb], CS_LD, wmma::mem_row_major);
        __syncwarp();
#pragma unroll
        for (int i = lane; i < 128; i += 32) {       // 16 rows x 8 col-pairs
            int r = i >> 3, cp = i & 7;
            int gm = m0 + wid * 16 + r;
            if (gm < M) {
                int col = nb * 16 + cp * 2;
                float2 bv = __ldg(reinterpret_cast<const float2*>(&bias[col]));
                float v0 = Cs[wid][r * CS_LD + cp * 2 + 0] + bv.x;
                float v1 = Cs[wid][r * CS_LD + cp * 2 + 1] + bv.y;
                Z[(size_t)gm * (H / 2) + (col >> 1)] =
                    __float22half2_rn(make_float2(v0, v1));
            }
        }
        __syncwarp();
    }
}

// ---------------- aggregation: warp per node, fp16 gathers, fp16 out ----------
__global__ void __launch_bounds__(256)
agg_leaky_kernel(const uint2* __restrict__ z, uint2* __restrict__ outh)
{
    int node = blockIdx.x * 8 + (threadIdx.x >> 5);
    if (node >= N_NODES) return;
    int lane = threadIdx.x & 31;   // lane owns features [4*lane, 4*lane+4)
    int beg = g_row_ptr[node];
    int end = g_row_ptr[node + 1];

    float4 acc = make_float4(0.f, 0.f, 0.f, 0.f);
    int e = beg;
    for (; e + 4 <= end; e += 4) {
        int2 p0 = __ldg(&g_csr[e + 0]);
        int2 p1 = __ldg(&g_csr[e + 1]);
        int2 p2 = __ldg(&g_csr[e + 2]);
        int2 p3 = __ldg(&g_csr[e + 3]);
        uint2 v0 = z[p0.x * 32 + lane];
        uint2 v1 = z[p1.x * 32 + lane];
        uint2 v2 = z[p2.x * 32 + lane];
        uint2 v3 = z[p3.x * 32 + lane];
        float w0 = __int_as_float(p0.y);
        float w1 = __int_as_float(p1.y);
        float w2 = __int_as_float(p2.y);
        float w3 = __int_as_float(p3.y);
        float2 a0 = __half22float2(*(const __half2*)&v0.x);
        float2 b0 = __half22float2(*(const __half2*)&v0.y);
        float2 a1 = __half22float2(*(const __half2*)&v1.x);
        float2 b1 = __half22float2(*(const __half2*)&v1.y);
        float2 a2 = __half22float2(*(const __half2*)&v2.x);
        float2 b2 = __half22float2(*(const __half2*)&v2.y);
        float2 a3 = __half22float2(*(const __half2*)&v3.x);
        float2 b3 = __half22float2(*(const __half2*)&v3.y);
        acc.x += a0.x * w0 + a1.x * w1 + a2.x * w2 + a3.x * w3;
        acc.y += a0.y * w0 + a1.y * w1 + a2.y * w2 + a3.y * w3;
        acc.z += b0.x * w0 + b1.x * w1 + b2.x * w2 + b3.x * w3;
        acc.w += b0.y * w0 + b1.y * w1 + b2.y * w2 + b3.y * w3;
    }
    for (; e < end; e++) {
        int2 p = __ldg(&g_csr[e]);
        uint2 v = z[p.x * 32 + lane];
        float w = __int_as_float(p.y);
        float2 a = __half22float2(*(const __half2*)&v.x);
        float2 b = __half22float2(*(const __half2*)&v.y);
        acc.x += a.x * w; acc.y += a.y * w;
        acc.z += b.x * w; acc.w += b.y * w;
    }
    float di = g_deg_inv[node];
    acc.x *= di; acc.y *= di; acc.z *= di; acc.w *= di;
    acc.x = (acc.x > 0.f) ? acc.x : 0.01f * acc.x;
    acc.y = (acc.y > 0.f) ? acc.y : 0.01f * acc.y;
    acc.z = (acc.z > 0.f) ? acc.z : 0.01f * acc.z;
    acc.w = (acc.w > 0.f) ? acc.w : 0.01f * acc.w;
    uint2 o;
    *(__half2*)&o.x = __float22half2_rn(make_float2(acc.x, acc.y));
    *(__half2*)&o.y = __float22half2_rn(make_float2(acc.z, acc.w));
    outh[node * 32 + lane] = o;
}

// ---------------- final FC: out[M,4] = h[M,128](fp16) @ Wfc[128,4] + bfc ----------
__global__ void fc_kernel(const uint2* __restrict__ h2, const float* __restrict__ Wfc,
                          const float* __restrict__ bfc, float* __restrict__ out, int M)
{
    int warp = (blockIdx.x * blockDim.x + threadIdx.x) >> 5;
    int lane = threadIdx.x & 31;
    if (warp >= M) return;
    uint2 v = h2[warp * 32 + lane];           // features 4*lane .. 4*lane+3
    float2 a = __half22float2(*(const __half2*)&v.x);
    float2 b = __half22float2(*(const __half2*)&v.y);
    float hv[4] = {a.x, a.y, b.x, b.y};
    float acc0 = 0.f, acc1 = 0.f, acc2 = 0.f, acc3 = 0.f;
#pragma unroll
    for (int j = 0; j < 4; j++) {
        int k = 4 * lane + j;
        float4 w = __ldg(reinterpret_cast<const float4*>(&Wfc[k * 4]));
        acc0 += hv[j] * w.x;
        acc1 += hv[j] * w.y;
        acc2 += hv[j] * w.z;
        acc3 += hv[j] * w.w;
    }
#pragma unroll
    for (int off = 16; off; off >>= 1) {
        acc0 += __shfl_down_sync(0xffffffffu, acc0, off);
        acc1 += __shfl_down_sync(0xffffffffu, acc1, off);
        acc2 += __shfl_down_sync(0xffffffffu, acc2, off);
        acc3 += __shfl_down_sync(0xffffffffu, acc3, off);
    }
    if (lane == 0) {
        out[warp * 4 + 0] = acc0 + bfc[0];
        out[warp * 4 + 1] = acc1 + bfc[1];
        out[warp * 4 + 2] = acc2 + bfc[2];
        out[warp * 4 + 3] = acc3 + bfc[3];
    }
}

// ---------------- launch ----------------
extern "C" void kernel_launch(void* const* d_in, const int* in_sizes, int n_in,
                              void* d_out, int out_size)
{
    const float* x          = (const float*)d_in[0];
    const int*   edge_index = (const int*)d_in[1];
    const float* edge_attr  = (const float*)d_in[2];
    const float* W_in       = (const float*)d_in[3];
    const float* b_in       = (const float*)d_in[4];
    const float* W_h        = (const float*)d_in[5];
    const float* b_h        = (const float*)d_in[6];
    const float* W_fc       = (const float*)d_in[7];
    const float* b_fc       = (const float*)d_in[8];
    float* out = (float*)d_out;

    const int* src = edge_index;            // row 0
    const int* dst = edge_index + N_EDGES;  // row 1

    __half *bufA, *bufZ, *Wh16;
    cudaGetSymbolAddress((void**)&bufA, g_bufA);
    cudaGetSymbolAddress((void**)&bufZ, g_bufZ);
    cudaGetSymbolAddress((void**)&Wh16, g_Wh16);

    // preprocessing: degree, CSR, weight conversion
    zero_counts_kernel<<<(N_NODES + 255) / 256, 256>>>();
    hist_kernel<<<(N_EDGES + 255) / 256, 256>>>(dst);
    convert_w_kernel<<<(N_HIDDEN * H * H + 255) / 256, 256>>>(W_h);
    scan_kernel<<<1, 1024>>>();
    fill_kernel<<<(N_EDGES + 255) / 256, 256>>>(src, dst, edge_attr);

    const int GEMM_GRID = (N_NODES + H - 1) / H;
    const int AGG_GRID  = (N_NODES + 7) / 8;

    // layer 0: x [N,16] fp32 -> z fp16 -> agg -> h fp16
    gemm_bias_kernel<IN_FEATS><<<GEMM_GRID, 256>>>(x, W_in, b_in, (__half2*)bufZ, N_NODES);
    agg_leaky_kernel<<<AGG_GRID, 256>>>((const uint2*)bufZ, (uint2*)bufA);

    // 19 hidden layers: WMMA GEMM + agg
    for (int l = 0; l < N_HIDDEN; l++) {
        hgemm_kernel<<<GEMM_GRID, 256>>>(bufA, Wh16 + (size_t)l * H * H,
                                         b_h + (size_t)l * H, (__half2*)bufZ, N_NODES);
        agg_leaky_kernel<<<AGG_GRID, 256>>>((const uint2*)bufZ, (uint2*)bufA);
    }

    // final FC: [N,128] fp16 @ [128,4] + b
    const int FC_THREADS = 256;
    const int warps_per_block = FC_THREADS / 32;
    fc_kernel<<<(N_NODES + warps_per_block - 1) / warps_per_block, FC_THREADS>>>(
        (const uint2*)bufA, W_fc, b_fc, out, N_NODES);
}

// round 10
// speedup vs baseline: 3.2118x; 1.0401x over previous
#include <cuda_runtime.h>
#include <cuda_fp16.h>
#include <mma.h>

#define N_NODES 50000
#define N_EDGES 600000
#define IN_FEATS 16
#define H 128
#define N_CLASSES 4
#define N_HIDDEN 19

#define DEG_PAD 53248   // 1024 threads * 52 elems, int4-aligned

using namespace nvcuda;

// ---------------- scratch (device globals; no allocation allowed) ----------------
__device__ __half g_bufA[N_NODES * H];          // fp16 h (agg output / GEMM input)
__device__ __half g_bufZ[N_NODES * H];          // fp16 z (GEMM output / agg gather src)
__device__ __half g_Wh16[N_HIDDEN * H * H];     // fp16 hidden weights
__device__ __align__(16) int g_deg[DEG_PAD];    // padded for int4 scan loads
__device__ int    g_cnt[N_NODES];
__device__ int    g_row_ptr[N_NODES + 1];
__device__ float  g_deg_inv[N_NODES];
__device__ int2   g_csr[N_EDGES];               // {src, float_as_int(w)} per edge

// ---------------- preprocessing ----------------
__global__ void zero_counts_kernel() {
    int i = blockIdx.x * blockDim.x + threadIdx.x;
    if (i < DEG_PAD) g_deg[i] = 0;
    if (i < N_NODES) g_cnt[i] = 0;
}

__global__ void hist_kernel(const int* __restrict__ dst) {
    int i = blockIdx.x * blockDim.x + threadIdx.x;
    if (i < N_EDGES) atomicAdd(&g_deg[dst[i]], 1);
}

__global__ void convert_w_kernel(const float* __restrict__ W) {
    int i = blockIdx.x * blockDim.x + threadIdx.x;     // one float4 -> one uint2(half4)
    if (i < N_HIDDEN * H * H / 4) {
        float4 v = __ldg(reinterpret_cast<const float4*>(W) + i);
        uint2 o;
        *(__half2*)&o.x = __float22half2_rn(make_float2(v.x, v.y));
        *(__half2*)&o.y = __float22half2_rn(make_float2(v.z, v.w));
        reinterpret_cast<uint2*>(g_Wh16)[i] = o;
    }
}

// single-block exclusive scan; int4 batched loads (high MLP) kill the latency chain.
// __launch_bounds__(1024) caps regs at 64/thread (spills are L1-resident, fine).
__global__ void __launch_bounds__(1024) scan_kernel() {
    __shared__ int sums[1024];
    int tid = threadIdx.x;
    int beg = tid * 52;

    int4 v[13];
    const int4* dp = reinterpret_cast<const int4*>(g_deg);
#pragma unroll
    for (int j = 0; j < 13; j++) v[j] = dp[tid * 13 + j];

    int s = 0;
#pragma unroll
    for (int j = 0; j < 13; j++) s += v[j].x + v[j].y + v[j].z + v[j].w;
    sums[tid] = s;
    __syncthreads();
    for (int off = 1; off < 1024; off <<= 1) {
        int t = 0;
        if (tid >= off) t = sums[tid - off];
        __syncthreads();
        sums[tid] += t;
        __syncthreads();
    }
    int prefix = (tid == 0) ? 0 : sums[tid - 1];

    if (beg + 52 <= N_NODES) {          // fast path: all 52 in range (uniform branch)
#pragma unroll
        for (int j = 0; j < 13; j++) {
            int i = beg + 4 * j;
            g_row_ptr[i + 0] = prefix; g_deg_inv[i + 0] = 1.0f / fmaxf((float)v[j].x, 1.0f); prefix += v[j].x;
            g_row_ptr[i + 1] = prefix; g_deg_inv[i + 1] = 1.0f / fmaxf((float)v[j].y, 1.0f); prefix += v[j].y;
            g_row_ptr[i + 2] = prefix; g_deg_inv[i + 2] = 1.0f / fmaxf((float)v[j].z, 1.0f); prefix += v[j].z;
            g_row_ptr[i + 3] = prefix; g_deg_inv[i + 3] = 1.0f / fmaxf((float)v[j].w, 1.0f); prefix += v[j].w;
        }
    } else {
#pragma unroll
        for (int j = 0; j < 13; j++) {
            int d[4] = {v[j].x, v[j].y, v[j].z, v[j].w};
#pragma unroll
            for (int q = 0; q < 4; q++) {
                int i = beg + 4 * j + q;
                if (i < N_NODES) {
                    g_row_ptr[i] = prefix;
                    g_deg_inv[i] = 1.0f / fmaxf((float)d[q], 1.0f);
                }
                prefix += d[q];
            }
        }
    }
    if (tid == 1023) g_row_ptr[N_NODES] = sums[1023];
}

__global__ void fill_kernel(const int* __restrict__ src, const int* __restrict__ dst,
                            const float* __restrict__ ew) {
    int i = blockIdx.x * blockDim.x + threadIdx.x;
    if (i < N_EDGES) {
        int d = dst[i];
        int pos = g_row_ptr[d] + atomicAdd(&g_cnt[d], 1);
        g_csr[pos] = make_int2(src[i], __float_as_int(ew[i]));
    }
}

// ---------------- layer-0 GEMM (fp32 in, FFMA2, fp16 out): K=16 ----------------
template<int K>
__global__ void __launch_bounds__(256)
gemm_bias_kernel(const float* __restrict__ A, const float* __restrict__ W,
                 const float* __restrict__ bias, __half2* __restrict__ Z, int M)
{
    const int BK = 16;
    __shared__ float As[BK][H + 1];
    __shared__ float Ws[BK][H];
    int tid = threadIdx.x;
    int tx = tid & 15;
    int ty = tid >> 4;
    int m0 = blockIdx.x * H;

    unsigned long long acc[8][4];
#pragma unroll
    for (int r = 0; r < 8; r++)
#pragma unroll
        for (int c = 0; c < 4; c++) acc[r][c] = 0ull;

    for (int k0 = 0; k0 < K; k0 += BK) {
#pragma unroll
        for (int i = tid; i < H * BK; i += 256) {
            int m = i >> 4, k = i & 15;
            int gm = m0 + m;
            As[k][m] = (gm < M) ? A[gm * K + k0 + k] : 0.f;
        }
#pragma unroll
        for (int i = tid; i < BK * H; i += 256) {
            int k = i >> 7, n = i & (H - 1);
            Ws[k][n] = W[(k0 + k) * H + n];
        }
        __syncthreads();
#pragma unroll
        for (int k = 0; k < BK; k++) {
            unsigned long long ad[8];
#pragma unroll
            for (int r = 0; r < 8; r++) {
                float av = As[k][ty + r * 16];
                asm("mov.b64 %0, {%1, %1};" : "=l"(ad[r]) : "f"(av));
            }
            unsigned long long wd[4];
#pragma unroll
            for (int c = 0; c < 4; c++) {
                wd[c] = *reinterpret_cast<const unsigned long long*>(&Ws[k][2 * tx + 32 * c]);
            }
#pragma unroll
            for (int r = 0; r < 8; r++)
#pragma unroll
                for (int c = 0; c < 4; c++)
                    asm("fma.rn.f32x2 %0, %1, %2, %0;"
                        : "+l"(acc[r][c]) : "l"(ad[r]), "l"(wd[c]));
        }
        __syncthreads();
    }

#pragma unroll
    for (int r = 0; r < 8; r++) {
        int gm = m0 + ty + r * 16;
        if (gm < M) {
#pragma unroll
            for (int c = 0; c < 4; c++) {
                int n = 2 * tx + 32 * c;
                float lo, hi;
                asm("mov.b64 {%0, %1}, %2;" : "=f"(lo), "=f"(hi) : "l"(acc[r][c]));
                float2 bv = *reinterpret_cast<const float2*>(&bias[n]);
                Z[gm * (H / 2) + (n >> 1)] =
                    __float22half2_rn(make_float2(lo + bv.x, hi + bv.y));
            }
        }
    }
}

// ---------------- hidden GEMM: Z[M,128] = h[M,128](fp16) @ Wh(fp16) + b, WMMA ----
#define AS_LD 40     // halfs per As row (32 + 8 pad)
#define WS_LD 136    // halfs per Ws row (128 + 8 pad)
#define CS_LD 20     // floats per staging row (16 + 4 pad)

__global__ void __launch_bounds__(256)
hgemm_kernel(const __half* __restrict__ A, const __half* __restrict__ Wh,
             const float* __restrict__ bias, __half2* __restrict__ Z, int M)
{
    __shared__ __align__(16) __half As[128 * AS_LD];
    __shared__ __align__(16) __half Ws[32 * WS_LD];
    __shared__ __align__(16) float  Cs[8][16 * CS_LD];
    int tid = threadIdx.x;
    int wid = tid >> 5;
    int lane = tid & 31;
    int m0 = blockIdx.x * 128;

    wmma::fragment<wmma::accumulator, 16, 16, 16, float> acc[8];
#pragma unroll
    for (int nb = 0; nb < 8; nb++) wmma::fill_fragment(acc[nb], 0.0f);

    for (int k0 = 0; k0 < H; k0 += 32) {
#pragma unroll
        for (int i = tid; i < 512; i += 256) {
            int ri = i >> 2, ci = i & 3;
            int gm = m0 + ri;
            uint4 v = make_uint4(0u, 0u, 0u, 0u);
            if (gm < M)
                v = *reinterpret_cast<const uint4*>(A + (size_t)gm * H + k0 + ci * 8);
            *reinterpret_cast<uint4*>(As + ri * AS_LD + ci * 8) = v;
        }
#pragma unroll
        for (int i = tid; i < 512; i += 256) {
            int ri = i >> 4, ci = i & 15;
            uint4 v = *reinterpret_cast<const uint4*>(Wh + (size_t)(k0 + ri) * H + ci * 8);
            *reinterpret_cast<uint4*>(Ws + ri * WS_LD + ci * 8) = v;
        }
        __syncthreads();

#pragma unroll
        for (int ks = 0; ks < 2; ks++) {
            wmma::fragment<wmma::matrix_a, 16, 16, 16, __half, wmma::row_major> af;
            wmma::load_matrix_sync(af, As + (wid * 16) * AS_LD + ks * 16, AS_LD);
#pragma unroll
            for (int nb = 0; nb < 8; nb++) {
                wmma::fragment<wmma::matrix_b, 16, 16, 16, __half, wmma::row_major> bf;
                wmma::load_matrix_sync(bf, Ws + (ks * 16) * WS_LD + nb * 16, WS_LD);
                wmma::mma_sync(acc[nb], af, bf, acc[nb]);
            }
        }
        __syncthreads();
    }

#pragma unroll
    for (int nb = 0; nb < 8; nb++) {
        wmma::store_matrix_sync(&Cs[wid][0], acc[nb], CS_LD, wmma::mem_row_major);
        __syncwarp();
#pragma unroll
        for (int i = lane; i < 128; i += 32) {
            int r = i >> 3, cp = i & 7;
            int gm = m0 + wid * 16 + r;
            if (gm < M) {
                int col = nb * 16 + cp * 2;
                float2 bv = __ldg(reinterpret_cast<const float2*>(&bias[col]));
                float v0 = Cs[wid][r * CS_LD + cp * 2 + 0] + bv.x;
                float v1 = Cs[wid][r * CS_LD + cp * 2 + 1] + bv.y;
                Z[(size_t)gm * (H / 2) + (col >> 1)] =
                    __float22half2_rn(make_float2(v0, v1));
            }
        }
        __syncwarp();
    }
}

// ---------------- aggregation: warp per node, fp16 gathers, unroll-8 ----------
__global__ void __launch_bounds__(256)
agg_leaky_kernel(const uint2* __restrict__ z, uint2* __restrict__ outh)
{
    int node = blockIdx.x * 8 + (threadIdx.x >> 5);
    if (node >= N_NODES) return;
    int lane = threadIdx.x & 31;   // lane owns features [4*lane, 4*lane+4)
    int beg = g_row_ptr[node];
    int end = g_row_ptr[node + 1];

    float4 acc = make_float4(0.f, 0.f, 0.f, 0.f);
    int e = beg;
    for (; e + 8 <= end; e += 8) {
        int2 p[8];
#pragma unroll
        for (int j = 0; j < 8; j++) p[j] = __ldg(&g_csr[e + j]);
        uint2 v[8];
#pragma unroll
        for (int j = 0; j < 8; j++) v[j] = z[p[j].x * 32 + lane];
#pragma unroll
        for (int j = 0; j < 8; j++) {
            float w = __int_as_float(p[j].y);
            float2 a = __half22float2(*(const __half2*)&v[j].x);
            float2 b = __half22float2(*(const __half2*)&v[j].y);
            acc.x += a.x * w; acc.y += a.y * w;
            acc.z += b.x * w; acc.w += b.y * w;
        }
    }
    for (; e + 4 <= end; e += 4) {
        int2 p[4];
#pragma unroll
        for (int j = 0; j < 4; j++) p[j] = __ldg(&g_csr[e + j]);
        uint2 v[4];
#pragma unroll
        for (int j = 0; j < 4; j++) v[j] = z[p[j].x * 32 + lane];
#pragma unroll
        for (int j = 0; j < 4; j++) {
            float w = __int_as_float(p[j].y);
            float2 a = __half22float2(*(const __half2*)&v[j].x);
            float2 b = __half22float2(*(const __half2*)&v[j].y);
            acc.x += a.x * w; acc.y += a.y * w;
            acc.z += b.x * w; acc.w += b.y * w;
        }
    }
    for (; e < end; e++) {
        int2 p = __ldg(&g_csr[e]);
        uint2 v = z[p.x * 32 + lane];
        float w = __int_as_float(p.y);
        float2 a = __half22float2(*(const __half2*)&v.x);
        float2 b = __half22float2(*(const __half2*)&v.y);
        acc.x += a.x * w; acc.y += a.y * w;
        acc.z += b.x * w; acc.w += b.y * w;
    }
    float di = g_deg_inv[node];
    acc.x *= di; acc.y *= di; acc.z *= di; acc.w *= di;
    acc.x = (acc.x > 0.f) ? acc.x : 0.01f * acc.x;
    acc.y = (acc.y > 0.f) ? acc.y : 0.01f * acc.y;
    acc.z = (acc.z > 0.f) ? acc.z : 0.01f * acc.z;
    acc.w = (acc.w > 0.f) ? acc.w : 0.01f * acc.w;
    uint2 o;
    *(__half2*)&o.x = __float22half2_rn(make_float2(acc.x, acc.y));
    *(__half2*)&o.y = __float22half2_rn(make_float2(acc.z, acc.w));
    outh[node * 32 + lane] = o;
}

// ---------------- final FC: out[M,4] = h[M,128](fp16) @ Wfc[128,4] + bfc ----------
__global__ void fc_kernel(const uint2* __restrict__ h2, const float* __restrict__ Wfc,
                          const float* __restrict__ bfc, float* __restrict__ out, int M)
{
    int warp = (blockIdx.x * blockDim.x + threadIdx.x) >> 5;
    int lane = threadIdx.x & 31;
    if (warp >= M) return;
    uint2 v = h2[warp * 32 + lane];           // features 4*lane .. 4*lane+3
    float2 a = __half22float2(*(const __half2*)&v.x);
    float2 b = __half22float2(*(const __half2*)&v.y);
    float hv[4] = {a.x, a.y, b.x, b.y};
    float acc0 = 0.f, acc1 = 0.f, acc2 = 0.f, acc3 = 0.f;
#pragma unroll
    for (int j = 0; j < 4; j++) {
        int k = 4 * lane + j;
        float4 w = __ldg(reinterpret_cast<const float4*>(&Wfc[k * 4]));
        acc0 += hv[j] * w.x;
        acc1 += hv[j] * w.y;
        acc2 += hv[j] * w.z;
        acc3 += hv[j] * w.w;
    }
#pragma unroll
    for (int off = 16; off; off >>= 1) {
        acc0 += __shfl_down_sync(0xffffffffu, acc0, off);
        acc1 += __shfl_down_sync(0xffffffffu, acc1, off);
        acc2 += __shfl_down_sync(0xffffffffu, acc2, off);
        acc3 += __shfl_down_sync(0xffffffffu, acc3, off);
    }
    if (lane == 0) {
        out[warp * 4 + 0] = acc0 + bfc[0];
        out[warp * 4 + 1] = acc1 + bfc[1];
        out[warp * 4 + 2] = acc2 + bfc[2];
        out[warp * 4 + 3] = acc3 + bfc[3];
    }
}

// ---------------- launch ----------------
extern "C" void kernel_launch(void* const* d_in, const int* in_sizes, int n_in,
                              void* d_out, int out_size)
{
    const float* x          = (const float*)d_in[0];
    const int*   edge_index = (const int*)d_in[1];
    const float* edge_attr  = (const float*)d_in[2];
    const float* W_in       = (const float*)d_in[3];
    const float* b_in       = (const float*)d_in[4];
    const float* W_h        = (const float*)d_in[5];
    const float* b_h        = (const float*)d_in[6];
    const float* W_fc       = (const float*)d_in[7];
    const float* b_fc       = (const float*)d_in[8];
    float* out = (float*)d_out;

    const int* src = edge_index;            // row 0
    const int* dst = edge_index + N_EDGES;  // row 1

    __half *bufA, *bufZ, *Wh16;
    cudaGetSymbolAddress((void**)&bufA, g_bufA);
    cudaGetSymbolAddress((void**)&bufZ, g_bufZ);
    cudaGetSymbolAddress((void**)&Wh16, g_Wh16);

    // preprocessing: degree, CSR, weight conversion
    zero_counts_kernel<<<(DEG_PAD + 255) / 256, 256>>>();
    hist_kernel<<<(N_EDGES + 255) / 256, 256>>>(dst);
    convert_w_kernel<<<(N_HIDDEN * H * H / 4 + 255) / 256, 256>>>(W_h);
    scan_kernel<<<1, 1024>>>();
    fill_kernel<<<(N_EDGES + 255) / 256, 256>>>(src, dst, edge_attr);

    const int GEMM_GRID = (N_NODES + H - 1) / H;
    const int AGG_GRID  = (N_NODES + 7) / 8;

    // layer 0: x [N,16] fp32 -> z fp16 -> agg -> h fp16
    gemm_bias_kernel<IN_FEATS><<<GEMM_GRID, 256>>>(x, W_in, b_in, (__half2*)bufZ, N_NODES);
    agg_leaky_kernel<<<AGG_GRID, 256>>>((const uint2*)bufZ, (uint2*)bufA);

    // 19 hidden layers: WMMA GEMM + agg
    for (int l = 0; l < N_HIDDEN; l++) {
        hgemm_kernel<<<GEMM_GRID, 256>>>(bufA, Wh16 + (size_t)l * H * H,
                                         b_h + (size_t)l * H, (__half2*)bufZ, N_NODES);
        agg_leaky_kernel<<<AGG_GRID, 256>>>((const uint2*)bufZ, (uint2*)bufA);
    }

    // final FC: [N,128] fp16 @ [128,4] + b
    const int FC_THREADS = 256;
    const int warps_per_block = FC_THREADS / 32;
    fc_kernel<<<(N_NODES + warps_per_block - 1) / warps_per_block, FC_THREADS>>>(
        (const uint2*)bufA, W_fc, b_fc, out, N_NODES);
}